// round 14
// baseline (speedup 1.0000x reference)
#include <cuda_runtime.h>
#include <math.h>
#include <stdint.h>

#define BDIM 4096
#define RDIM 64
#define DDIM 512
#define BB   16
#define NBLOCK (BDIM / BB)      // 256 CTAs -> 2 per SM
#define NTHREADS 256
#define KC   64                 // K per chunk (8 chunks)
#define RF4  20                 // float4 per padded row (20 mod 8 == 4 -> conflict-free)
#define ROWFL (RF4 * 4)         // 80 floats
// buffer layout (floats): w_hi 16 rows | w_lo 16 | e_hi 64 | e_lo 64  = 160 rows
#define WLO_F (16 * ROWFL)      // 1280
#define EHI_F (32 * ROWFL)      // 2560
#define ELO_F (96 * ROWFL)      // 7680
#define BUF_F (160 * ROWFL)     // 12800 floats
#define DYN_SMEM (2 * BUF_F * 4)   // 102400 B  -> 2 CTAs/SM

__device__ float g_partial[NBLOCK];
__device__ int   g_count = 0;

__device__ __forceinline__ uint32_t smem_u32(const void* p) {
    return (uint32_t)__cvta_generic_to_shared(p);
}
__device__ __forceinline__ void bulk_cp(uint32_t dst, const void* src,
                                        uint32_t bytes, uint32_t mbar) {
    asm volatile(
        "cp.async.bulk.shared::cta.global.mbarrier::complete_tx::bytes [%0], [%1], %2, [%3];"
        :: "r"(dst), "l"(src), "r"(bytes), "r"(mbar) : "memory");
}
__device__ __forceinline__ void mbar_init(uint32_t mbar, uint32_t cnt) {
    asm volatile("mbarrier.init.shared.b64 [%0], %1;" :: "r"(mbar), "r"(cnt) : "memory");
}
__device__ __forceinline__ void mbar_expect_tx(uint32_t mbar, uint32_t bytes) {
    asm volatile("mbarrier.arrive.expect_tx.shared.b64 _, [%0], %1;"
                 :: "r"(mbar), "r"(bytes) : "memory");
}
__device__ __forceinline__ void mbar_wait(uint32_t mbar, uint32_t parity) {
    asm volatile(
        "{\n\t.reg .pred P;\n\t"
        "WL_%=:\n\t"
        "mbarrier.try_wait.parity.acquire.cta.shared::cta.b64 P, [%0], %1, 0x989680;\n\t"
        "@P bra.uni WD_%=;\n\t"
        "bra.uni WL_%=;\n\t"
        "WD_%=:\n\t}"
        :: "r"(mbar), "r"(parity) : "memory");
}
__device__ __forceinline__ void split1(float x, float& h, float& l) {
    h = __uint_as_float(__float_as_uint(x) & 0xFFFFE000u);
    l = x - h;
}
__device__ __forceinline__ void split4(float4 v, float4& h, float4& l) {
    split1(v.x, h.x, l.x); split1(v.y, h.y, l.y);
    split1(v.z, h.z, l.z); split1(v.w, h.w, l.w);
}
__device__ __forceinline__ void mma_tf32(float* c, const uint32_t* a,
                                         uint32_t b0, uint32_t b1) {
    asm volatile(
        "mma.sync.aligned.m16n8k8.row.col.f32.tf32.tf32.f32 "
        "{%0,%1,%2,%3}, {%4,%5,%6,%7}, {%8,%9}, {%0,%1,%2,%3};"
        : "+f"(c[0]), "+f"(c[1]), "+f"(c[2]), "+f"(c[3])
        : "r"(a[0]), "r"(a[1]), "r"(a[2]), "r"(a[3]), "r"(b0), "r"(b1));
}

__global__ __launch_bounds__(NTHREADS, 2)
void fused_kernel(const float* __restrict__ w,
                  const float* __restrict__ e,
                  const float* __restrict__ label,
                  float* __restrict__ out, int out_size)
{
    extern __shared__ __align__(16) float dyn[];

    __shared__ __align__(8) uint64_t mbar_sto[8];
    __shared__ float ne_red[RDIM][5];
    __shared__ float ne_s[RDIM];
    __shared__ float nw_red[BB][17];
    __shared__ int   idx1_s[BB];
    __shared__ float fs[NBLOCK];
    __shared__ int   is_last;

    const int tid  = threadIdx.x;
    const int lane = tid & 31;
    const int wid  = tid >> 5;
    const int b0   = blockIdx.x * BB;

    // s_s aliases buffer 0 (last read by chunk 6's MMAs)
    float (*s_s)[65] = reinterpret_cast<float (*)[65]>(dyn);

    uint32_t mbars[8];
#pragma unroll
    for (int q = 0; q < 8; q++) mbars[q] = smem_u32(&mbar_sto[q]);

    if (tid == 0) {
#pragma unroll
        for (int q = 0; q < 8; q++) mbar_init(mbars[q], 1);
    }
    __syncthreads();
    if (tid == 0) {
#pragma unroll
        for (int q = 0; q < 8; q++) mbar_expect_tx(mbars[q], 80 * KC * 4);
    }
    __syncthreads();

    auto issue_chunk = [&](int q) {
        if (tid < 80) {
            float* B = dyn + (q & 1) * BUF_F;
            if (tid < BB)
                bulk_cp(smem_u32(B + tid * ROWFL),
                        w + (size_t)(b0 + tid) * DDIM + q * KC, KC * 4, mbars[q]);
            else {
                int r = tid - BB;
                bulk_cp(smem_u32(B + EHI_F + r * ROWFL),
                        e + (size_t)r * DDIM + q * KC, KC * 4, mbars[q]);
            }
        }
    };
    issue_chunk(0);
    issue_chunk(1);

    // warp tile: (kh, nq); 16 rows x 16 cols, K split by kh within each chunk
    const int kh = wid >> 2;          // 0..1
    const int nq = wid & 3;           // 0..3
    const int gi = lane >> 2;         // 0..7
    const int kk = lane & 3;          // 0..3
    const int r_lo = gi;

    // split-pass mapping (conflict-free checked mod 8 at stride 20 f4)
    const int w_row = tid >> 4, w_c = tid & 15;    // 16 thr/row, 1 f4 each
    const int e_row = tid >> 2, e_c = tid & 3;     // 4 thr/row, 4 f4 each

    float acc[2][3][4];               // [n-tile][term hh/hl/lh][4]
#pragma unroll
    for (int t = 0; t < 2; t++)
#pragma unroll
        for (int q = 0; q < 3; q++)
#pragma unroll
            for (int i = 0; i < 4; i++) acc[t][q][i] = 0.f;

    float nw_acc = 0.f, ne_acc = 0.f;

    for (int q = 0; q < 8; q++) {
        float* B = dyn + (q & 1) * BUF_F;
        mbar_wait(mbars[q], 0);

        // ---- split pass: raw -> hi in place + lo; norms ride along ----
        {
            float4* wr = reinterpret_cast<float4*>(B + w_row * ROWFL);
            float4* wl = reinterpret_cast<float4*>(B + WLO_F + w_row * ROWFL);
            {
                float4 v = wr[w_c];
                float4 h, l; split4(v, h, l);
                wr[w_c] = h; wl[w_c] = l;
                nw_acc = fmaf(v.x, v.x, nw_acc); nw_acc = fmaf(v.y, v.y, nw_acc);
                nw_acc = fmaf(v.z, v.z, nw_acc); nw_acc = fmaf(v.w, v.w, nw_acc);
            }
            float4* er = reinterpret_cast<float4*>(B + EHI_F + e_row * ROWFL);
            float4* el = reinterpret_cast<float4*>(B + ELO_F + e_row * ROWFL);
#pragma unroll
            for (int j = 0; j < 4; j++) {
                int k4 = e_c + 4 * j;
                float4 v = er[k4];
                float4 h, l; split4(v, h, l);
                er[k4] = h; el[k4] = l;
                ne_acc = fmaf(v.x, v.x, ne_acc); ne_acc = fmaf(v.y, v.y, ne_acc);
                ne_acc = fmaf(v.z, v.z, ne_acc); ne_acc = fmaf(v.w, v.w, ne_acc);
            }
        }
        __syncthreads();   // splits visible

        // ---- pure LDS + HMMA: this warp's 2 of the chunk's 4 blocks ----
        const float4* wlh = reinterpret_cast<const float4*>(B) + r_lo * RF4;
        const float4* whh = wlh + 8 * RF4;
        const float4* wll = reinterpret_cast<const float4*>(B + WLO_F) + r_lo * RF4;
        const float4* whl = wll + 8 * RF4;
        const float4* e0h = reinterpret_cast<const float4*>(B + EHI_F) + (16 * nq + gi) * RF4;
        const float4* e1h = e0h + 8 * RF4;
        const float4* e0l = reinterpret_cast<const float4*>(B + ELO_F) + (16 * nq + gi) * RF4;
        const float4* e1l = e0l + 8 * RF4;

#pragma unroll
        for (int blk = 0; blk < 2; blk++) {
            const int o = 4 * (kh * 2 + blk) + kk;
            float4 WLh = wlh[o], WHh = whh[o], WLl = wll[o], WHl = whl[o];
            float4 E0h = e0h[o], E0l = e0l[o], E1h = e1h[o], E1l = e1l[o];

            uint32_t ah0[4] = {__float_as_uint(WLh.x), __float_as_uint(WHh.x),
                               __float_as_uint(WLh.y), __float_as_uint(WHh.y)};
            uint32_t al0[4] = {__float_as_uint(WLl.x), __float_as_uint(WHl.x),
                               __float_as_uint(WLl.y), __float_as_uint(WHl.y)};
            uint32_t ah1[4] = {__float_as_uint(WLh.z), __float_as_uint(WHh.z),
                               __float_as_uint(WLh.w), __float_as_uint(WHh.w)};
            uint32_t al1[4] = {__float_as_uint(WLl.z), __float_as_uint(WHl.z),
                               __float_as_uint(WLl.w), __float_as_uint(WHl.w)};

            mma_tf32(acc[0][0], ah0, __float_as_uint(E0h.x), __float_as_uint(E0h.y));
            mma_tf32(acc[0][1], ah0, __float_as_uint(E0l.x), __float_as_uint(E0l.y));
            mma_tf32(acc[0][2], al0, __float_as_uint(E0h.x), __float_as_uint(E0h.y));
            mma_tf32(acc[1][0], ah0, __float_as_uint(E1h.x), __float_as_uint(E1h.y));
            mma_tf32(acc[1][1], ah0, __float_as_uint(E1l.x), __float_as_uint(E1l.y));
            mma_tf32(acc[1][2], al0, __float_as_uint(E1h.x), __float_as_uint(E1h.y));
            mma_tf32(acc[0][0], ah1, __float_as_uint(E0h.z), __float_as_uint(E0h.w));
            mma_tf32(acc[0][1], ah1, __float_as_uint(E0l.z), __float_as_uint(E0l.w));
            mma_tf32(acc[0][2], al1, __float_as_uint(E0h.z), __float_as_uint(E0h.w));
            mma_tf32(acc[1][0], ah1, __float_as_uint(E1h.z), __float_as_uint(E1h.w));
            mma_tf32(acc[1][1], ah1, __float_as_uint(E1l.z), __float_as_uint(E1l.w));
            mma_tf32(acc[1][2], al1, __float_as_uint(E1h.z), __float_as_uint(E1h.w));
        }
        __syncthreads();   // all warps done reading buffer q&1
        if (q + 2 < 8) issue_chunk(q + 2);   // overwrite now-free buffer, async
    }

    // ---- combine terms, two-phase deterministic kh merge into s_s ----
    float part[2][4];
#pragma unroll
    for (int t = 0; t < 2; t++)
#pragma unroll
        for (int i = 0; i < 4; i++)
            part[t][i] = (acc[t][0][i] + acc[t][1][i]) + acc[t][2][i];

    if (kh == 0) {
#pragma unroll
        for (int t = 0; t < 2; t++) {
            const int cb = 16 * nq + 8 * t + 2 * kk;
            s_s[r_lo][cb]     = part[t][0];
            s_s[r_lo][cb + 1] = part[t][1];
            s_s[r_lo + 8][cb]     = part[t][2];
            s_s[r_lo + 8][cb + 1] = part[t][3];
        }
    }
    nw_red[w_row][w_c] = nw_acc;
    ne_red[e_row][e_c] = ne_acc;
    __syncthreads();
    if (kh == 1) {
#pragma unroll
        for (int t = 0; t < 2; t++) {
            const int cb = 16 * nq + 8 * t + 2 * kk;
            s_s[r_lo][cb]     += part[t][0];
            s_s[r_lo][cb + 1] += part[t][1];
            s_s[r_lo + 8][cb]     += part[t][2];
            s_s[r_lo + 8][cb + 1] += part[t][3];
        }
    }
    if (tid < RDIM)
        ne_s[tid] = ne_red[tid][0] + ne_red[tid][1] + ne_red[tid][2] + ne_red[tid][3];
    __syncthreads();

    // ---- per-row epilogue: thread tid < 16 owns row b0+tid ----
    if (tid < BB) {
        const int r = tid;
        int y = 0;
        {
            const float4* lp = reinterpret_cast<const float4*>(
                label + (size_t)(b0 + r) * RDIM);
            float lm = -1e30f;
#pragma unroll
            for (int g = 0; g < 16; g++) {
                float4 v = lp[g];
                if (v.x > lm) { lm = v.x; y = g * 4; }
                if (v.y > lm) { lm = v.y; y = g * 4 + 1; }
                if (v.z > lm) { lm = v.z; y = g * 4 + 2; }
                if (v.w > lm) { lm = v.w; y = g * 4 + 3; }
            }
        }
        float m1 = -1e30f, m2 = -1e30f, s_y = 0.f;
        int i1 = 0;
#pragma unroll
        for (int c = 0; c < RDIM; c++) {
            float sv = fmaf(-2.f, s_s[r][c], ne_s[c]);
            if (c == y) s_y = sv;
            if (sv > m1)      { m2 = m1; m1 = sv; i1 = c; }
            else if (sv > m2) { m2 = sv; }
        }
        float nw = 0.f;
#pragma unroll
        for (int k = 0; k < 16; k++) nw += nw_red[r][k];

        float plus2  = fmaxf(nw + s_y, 0.f);
        float minus2 = fmaxf(nw + ((i1 == y) ? m2 : m1), 0.f);
        float loss_b = 1.f + sqrtf(plus2) - sqrtf(minus2);
        idx1_s[r] = i1;
        // reduce over 16 lanes (lanes 0-15 all take this branch)
#pragma unroll
        for (int off = 8; off; off >>= 1)
            loss_b += __shfl_xor_sync(0x0000FFFFu, loss_b, off);
        if (tid == 0) g_partial[blockIdx.x] = loss_b;
    }
    __syncthreads();

    // ---- coalesced one-hot pred write (one float4 per thread) ----
    {
        float4* op = reinterpret_cast<float4*>(out + (size_t)b0 * RDIM);
        int bl = tid >> 4;              // local b row 0..15
        int r  = (tid & 15) * 4;        // relation offset
        int p  = idx1_s[bl];
        float4 v;
        v.x = (r + 0 == p) ? 1.f : 0.f;
        v.y = (r + 1 == p) ? 1.f : 0.f;
        v.z = (r + 2 == p) ? 1.f : 0.f;
        v.w = (r + 3 == p) ? 1.f : 0.f;
        op[tid] = v;
    }

    // ---- fused finalize: last block reduces g_partial deterministically ----
    if (tid == 0) {
        __threadfence();
        int c = atomicAdd(&g_count, 1);
        is_last = (c == gridDim.x - 1) ? 1 : 0;
    }
    __syncthreads();
    if (is_last) {
        __threadfence();
        fs[tid] = g_partial[tid];          // NBLOCK == NTHREADS == 256
        __syncthreads();
#pragma unroll
        for (int off = NBLOCK / 2; off > 0; off >>= 1) {
            if (tid < off) fs[tid] += fs[tid + off];
            __syncthreads();
        }
        if (tid == 0) {
            out[out_size - 1] = fs[0] * (1.0f / (float)BDIM);
            g_count = 0;
        }
    }
}

extern "C" void kernel_launch(void* const* d_in, const int* in_sizes, int n_in,
                              void* d_out, int out_size)
{
    const float* w     = (const float*)d_in[0];   // [4096, 512]
    const float* e     = (const float*)d_in[1];   // [64, 512]
    const float* label = (const float*)d_in[2];   // [4096, 64]
    float* out = (float*)d_out;                   // pred [4096*64] ++ loss [1]

    cudaFuncSetAttribute(fused_kernel,
                         cudaFuncAttributeMaxDynamicSharedMemorySize, DYN_SMEM);
    fused_kernel<<<NBLOCK, NTHREADS, DYN_SMEM>>>(w, e, label, out, out_size);
}

// round 15
// speedup vs baseline: 1.1828x; 1.1828x over previous
#include <cuda_runtime.h>
#include <math.h>
#include <stdint.h>

#define BDIM 4096
#define RDIM 64
#define DDIM 512
#define BB   32
#define NBLOCK (BDIM / BB)      // 128 CTAs
#define NTHREADS 256
#define RF4  132                // float4 per padded row; 132 mod 8 == 4 -> conflict-free
#define ROWFL (RF4 * 4)         // 528 floats
#define W_TILE_F (BB * ROWFL)
#define E_TILE_F (RDIM * ROWFL)
#define DYN_SMEM ((W_TILE_F + E_TILE_F) * 4)   // 202752 B

__device__ float g_partial[NBLOCK];
__device__ int   g_count = 0;

__device__ __forceinline__ uint32_t smem_u32(const void* p) {
    return (uint32_t)__cvta_generic_to_shared(p);
}
__device__ __forceinline__ void bulk_cp(uint32_t dst, const void* src,
                                        uint32_t bytes, uint32_t mbar) {
    asm volatile(
        "cp.async.bulk.shared::cta.global.mbarrier::complete_tx::bytes [%0], [%1], %2, [%3];"
        :: "r"(dst), "l"(src), "r"(bytes), "r"(mbar) : "memory");
}
__device__ __forceinline__ void mbar_init(uint32_t mbar, uint32_t cnt) {
    asm volatile("mbarrier.init.shared.b64 [%0], %1;" :: "r"(mbar), "r"(cnt) : "memory");
}
__device__ __forceinline__ void mbar_expect_tx(uint32_t mbar, uint32_t bytes) {
    asm volatile("mbarrier.arrive.expect_tx.shared.b64 _, [%0], %1;"
                 :: "r"(mbar), "r"(bytes) : "memory");
}
__device__ __forceinline__ void mbar_wait(uint32_t mbar, uint32_t parity) {
    asm volatile(
        "{\n\t.reg .pred P;\n\t"
        "WL_%=:\n\t"
        "mbarrier.try_wait.parity.acquire.cta.shared::cta.b64 P, [%0], %1, 0x989680;\n\t"
        "@P bra.uni WD_%=;\n\t"
        "bra.uni WL_%=;\n\t"
        "WD_%=:\n\t}"
        :: "r"(mbar), "r"(parity) : "memory");
}
// split fp32 into tf32-exact hi + residual lo (bit patterns)
__device__ __forceinline__ void split_u(float x, uint32_t& hi, uint32_t& lo) {
    uint32_t xb = __float_as_uint(x);
    hi = xb & 0xFFFFE000u;
    lo = __float_as_uint(x - __uint_as_float(hi));
}
__device__ __forceinline__ void mma_tf32(float* c, const uint32_t* a,
                                         uint32_t b0, uint32_t b1) {
    asm volatile(
        "mma.sync.aligned.m16n8k8.row.col.f32.tf32.tf32.f32 "
        "{%0,%1,%2,%3}, {%4,%5,%6,%7}, {%8,%9}, {%0,%1,%2,%3};"
        : "+f"(c[0]), "+f"(c[1]), "+f"(c[2]), "+f"(c[3])
        : "r"(a[0]), "r"(a[1]), "r"(a[2]), "r"(a[3]), "r"(b0), "r"(b1));
}

__global__ __launch_bounds__(NTHREADS, 1)
void fused_kernel(const float* __restrict__ w,
                  const float* __restrict__ e,
                  const float* __restrict__ label,
                  float* __restrict__ out, int out_size)
{
    extern __shared__ __align__(16) float dyn[];
    float* w_s = dyn;                 // [BB][ROWFL]
    float* e_s = dyn + W_TILE_F;      // [RDIM][ROWFL]

    __shared__ __align__(8) uint64_t mbar_sto;
    __shared__ float s_s[BB][65];
    __shared__ float ne_red[RDIM][4];
    __shared__ float ne_s[RDIM];
    __shared__ float nw_red[BB][9];
    __shared__ int   idx1_s[BB];
    __shared__ float fs[NBLOCK];
    __shared__ int   is_last;

    const int tid  = threadIdx.x;
    const int lane = tid & 31;
    const int wid  = tid >> 5;
    const int b0   = blockIdx.x * BB;
    const uint32_t mbar = smem_u32(&mbar_sto);

    // ---- single-shot staging: 96 bulk ops (fewest TMA ops) ----
    if (tid == 0) mbar_init(mbar, 1);
    __syncthreads();
    if (tid == 0) mbar_expect_tx(mbar, (BB + RDIM) * DDIM * 4);
    __syncthreads();
    if (tid < BB) {
        bulk_cp(smem_u32(w_s + tid * ROWFL),
                w + (size_t)(b0 + tid) * DDIM, DDIM * 4, mbar);
    } else if (tid < BB + RDIM) {
        int r = tid - BB;
        bulk_cp(smem_u32(e_s + r * ROWFL),
                e + (size_t)r * DDIM, DDIM * 4, mbar);
    }
    mbar_wait(mbar, 0);

    // ---- warp tile: (kh, nh); M=32 x N=16 x K=256 per warp ----
    const int kh = wid >> 2;          // 0..1
    const int nh = wid & 3;           // 0..3
    const int gi = lane >> 2;         // 0..7
    const int kk = lane & 3;          // 0..3

    const float4* wp = reinterpret_cast<const float4*>(w_s) + gi * RF4 + kh * 64 + kk;
    const float4* ep = reinterpret_cast<const float4*>(e_s) + (16 * nh + gi) * RF4 + kh * 64 + kk;

    float acc[2][2][3][4];            // [m-tile][n-tile][term hh/hl/lh][4]
#pragma unroll
    for (int m = 0; m < 2; m++)
#pragma unroll
        for (int n = 0; n < 2; n++)
#pragma unroll
            for (int q = 0; q < 3; q++)
#pragma unroll
                for (int i = 0; i < 4; i++) acc[m][n][q][i] = 0.f;

    // rotating raw-fragment buffers: 4 w rows (gi, +8, +16, +24) + 2 e rows
    float4 rw[2][4], re[2][2];
#pragma unroll
    for (int j = 0; j < 4; j++) rw[0][j] = wp[j * (8 * RF4)];
#pragma unroll
    for (int n = 0; n < 2; n++) re[0][n] = ep[n * (8 * RF4)];

#pragma unroll
    for (int blk = 0; blk < 16; blk++) {
        const int cur = blk & 1, nxt = cur ^ 1;
        if (blk < 15) {                   // prefetch next block's fragments
            const int o = 4 * (blk + 1);
#pragma unroll
            for (int j = 0; j < 4; j++) rw[nxt][j] = wp[j * (8 * RF4) + o];
#pragma unroll
            for (int n = 0; n < 2; n++) re[nxt][n] = ep[n * (8 * RF4) + o];
        }

        // split A fragments (2 m-tiles x 2 ksteps)
        uint32_t aH[2][2][4], aL[2][2][4];   // [m][kstep][4]
#pragma unroll
        for (int m = 0; m < 2; m++) {
            float4 v0 = rw[cur][2 * m];      // rows gi(+16m)
            float4 v1 = rw[cur][2 * m + 1];  // rows gi+8(+16m)
            split_u(v0.x, aH[m][0][0], aL[m][0][0]);
            split_u(v1.x, aH[m][0][1], aL[m][0][1]);
            split_u(v0.y, aH[m][0][2], aL[m][0][2]);
            split_u(v1.y, aH[m][0][3], aL[m][0][3]);
            split_u(v0.z, aH[m][1][0], aL[m][1][0]);
            split_u(v1.z, aH[m][1][1], aL[m][1][1]);
            split_u(v0.w, aH[m][1][2], aL[m][1][2]);
            split_u(v1.w, aH[m][1][3], aL[m][1][3]);
        }
        // split B fragments (2 n-tiles x 2 ksteps x (b0,b1))
        uint32_t bH[2][2][2], bL[2][2][2];   // [n][kstep][2]
#pragma unroll
        for (int n = 0; n < 2; n++) {
            float4 v = re[cur][n];
            split_u(v.x, bH[n][0][0], bL[n][0][0]);
            split_u(v.y, bH[n][0][1], bL[n][0][1]);
            split_u(v.z, bH[n][1][0], bL[n][1][0]);
            split_u(v.w, bH[n][1][1], bL[n][1][1]);
        }

        // 24 MMAs, 12 independent chains
#pragma unroll
        for (int s = 0; s < 2; s++)
#pragma unroll
            for (int m = 0; m < 2; m++)
#pragma unroll
                for (int n = 0; n < 2; n++) {
                    mma_tf32(acc[m][n][0], aH[m][s], bH[n][s][0], bH[n][s][1]);
                    mma_tf32(acc[m][n][1], aH[m][s], bL[n][s][0], bL[n][s][1]);
                    mma_tf32(acc[m][n][2], aL[m][s], bH[n][s][0], bH[n][s][1]);
                }
    }

    // ---- combine terms; two-phase deterministic kh merge into s_s ----
    float part[2][2][4];
#pragma unroll
    for (int m = 0; m < 2; m++)
#pragma unroll
        for (int n = 0; n < 2; n++)
#pragma unroll
            for (int i = 0; i < 4; i++)
                part[m][n][i] = (acc[m][n][0][i] + acc[m][n][1][i]) + acc[m][n][2][i];

    if (kh == 0) {
#pragma unroll
        for (int m = 0; m < 2; m++)
#pragma unroll
            for (int n = 0; n < 2; n++) {
                const int rb = 16 * m + gi;
                const int cb = 16 * nh + 8 * n + 2 * kk;
                s_s[rb][cb]         = part[m][n][0];
                s_s[rb][cb + 1]     = part[m][n][1];
                s_s[rb + 8][cb]     = part[m][n][2];
                s_s[rb + 8][cb + 1] = part[m][n][3];
            }
    }
    __syncthreads();
    if (kh == 1) {
#pragma unroll
        for (int m = 0; m < 2; m++)
#pragma unroll
            for (int n = 0; n < 2; n++) {
                const int rb = 16 * m + gi;
                const int cb = 16 * nh + 8 * n + 2 * kk;
                s_s[rb][cb]         += part[m][n][0];
                s_s[rb][cb + 1]     += part[m][n][1];
                s_s[rb + 8][cb]     += part[m][n][2];
                s_s[rb + 8][cb + 1] += part[m][n][3];
            }
    }

    // ---- norms from smem ----
    {   // ||e_r||^2: r = tid>>2 (0..63), slice = tid&3 (32 f4)
        const int r = tid >> 2, sl = tid & 3;
        const float4* p = reinterpret_cast<const float4*>(e_s) + r * RF4 + sl * 32;
        float a = 0.f;
#pragma unroll 8
        for (int k = 0; k < 32; k++) {
            float4 v = p[k];
            a = fmaf(v.x, v.x, a); a = fmaf(v.y, v.y, a);
            a = fmaf(v.z, v.z, a); a = fmaf(v.w, v.w, a);
        }
        ne_red[r][sl] = a;
    }
    {   // ||w_b||^2: bl = tid>>3 (0..31), slice = tid&7 (16 f4)
        const int bl = tid >> 3, sl = tid & 7;
        const float4* p = reinterpret_cast<const float4*>(w_s) + bl * RF4 + sl * 16;
        float a = 0.f;
#pragma unroll 4
        for (int k = 0; k < 16; k++) {
            float4 v = p[k];
            a = fmaf(v.x, v.x, a); a = fmaf(v.y, v.y, a);
            a = fmaf(v.z, v.z, a); a = fmaf(v.w, v.w, a);
        }
        nw_red[bl][sl] = a;
    }
    __syncthreads();
    if (tid < RDIM)
        ne_s[tid] = ne_red[tid][0] + ne_red[tid][1] + ne_red[tid][2] + ne_red[tid][3];
    __syncthreads();

    // ---- per-row epilogue: thread tid < 32 owns row b0+tid ----
    if (tid < BB) {
        const int r = tid;
        int y = 0;
        {
            const float4* lp = reinterpret_cast<const float4*>(
                label + (size_t)(b0 + r) * RDIM);
            float lm = -1e30f;
#pragma unroll
            for (int g = 0; g < 16; g++) {
                float4 v = lp[g];
                if (v.x > lm) { lm = v.x; y = g * 4; }
                if (v.y > lm) { lm = v.y; y = g * 4 + 1; }
                if (v.z > lm) { lm = v.z; y = g * 4 + 2; }
                if (v.w > lm) { lm = v.w; y = g * 4 + 3; }
            }
        }
        float m1 = -1e30f, m2 = -1e30f, s_y = 0.f;
        int i1 = 0;
#pragma unroll
        for (int c = 0; c < RDIM; c++) {
            float sv = fmaf(-2.f, s_s[r][c], ne_s[c]);
            if (c == y) s_y = sv;
            if (sv > m1)      { m2 = m1; m1 = sv; i1 = c; }
            else if (sv > m2) { m2 = sv; }
        }
        float nw = 0.f;
#pragma unroll
        for (int k = 0; k < 8; k++) nw += nw_red[r][k];

        float plus2  = fmaxf(nw + s_y, 0.f);
        float minus2 = fmaxf(nw + ((i1 == y) ? m2 : m1), 0.f);
        float loss_b = 1.f + sqrtf(plus2) - sqrtf(minus2);
        idx1_s[r] = i1;
#pragma unroll
        for (int off = 16; off; off >>= 1)
            loss_b += __shfl_xor_sync(0xFFFFFFFFu, loss_b, off);
        if (lane == 0) g_partial[blockIdx.x] = loss_b;
    }
    __syncthreads();

    // ---- coalesced one-hot pred write (2 float4 per thread) ----
    {
        float4* op = reinterpret_cast<float4*>(out + (size_t)b0 * RDIM);
#pragma unroll
        for (int k = 0; k < 2; k++) {
            int i  = tid * 8 + k * 4;
            int bl = i >> 6;
            int r  = i & 63;
            int p  = idx1_s[bl];
            float4 v;
            v.x = (r + 0 == p) ? 1.f : 0.f;
            v.y = (r + 1 == p) ? 1.f : 0.f;
            v.z = (r + 2 == p) ? 1.f : 0.f;
            v.w = (r + 3 == p) ? 1.f : 0.f;
            op[tid * 2 + k] = v;
        }
    }

    // ---- fused finalize ----
    if (tid == 0) {
        __threadfence();
        int c = atomicAdd(&g_count, 1);
        is_last = (c == gridDim.x - 1) ? 1 : 0;
    }
    __syncthreads();
    if (is_last) {
        __threadfence();
        if (tid < NBLOCK) fs[tid] = g_partial[tid];
        __syncthreads();
#pragma unroll
        for (int off = NBLOCK / 2; off > 0; off >>= 1) {
            if (tid < off) fs[tid] += fs[tid + off];
            __syncthreads();
        }
        if (tid == 0) {
            out[out_size - 1] = fs[0] * (1.0f / (float)BDIM);
            g_count = 0;
        }
    }
}

extern "C" void kernel_launch(void* const* d_in, const int* in_sizes, int n_in,
                              void* d_out, int out_size)
{
    const float* w     = (const float*)d_in[0];   // [4096, 512]
    const float* e     = (const float*)d_in[1];   // [64, 512]
    const float* label = (const float*)d_in[2];   // [4096, 64]
    float* out = (float*)d_out;                   // pred [4096*64] ++ loss [1]

    cudaFuncSetAttribute(fused_kernel,
                         cudaFuncAttributeMaxDynamicSharedMemorySize, DYN_SMEM);
    fused_kernel<<<NBLOCK, NTHREADS, DYN_SMEM>>>(w, e, label, out, out_size);
}

// round 17
// speedup vs baseline: 1.4830x; 1.2538x over previous
#include <cuda_runtime.h>
#include <cuda_fp16.h>
#include <math.h>
#include <stdint.h>
#include <string.h>

#define BDIM 4096
#define RDIM 64
#define DDIM 512
#define BB   32
#define NBLOCK (BDIM / BB)      // 128 CTAs
#define NTHREADS 256
#define KC   128                // K per chunk
#define NCHUNK 4

// raw fp32 area: row = 128 floats -> 36 float4 padded (36 mod 8 == 4)
#define RAW_ROW4 36
#define RAW_B   ((BB + RDIM) * RAW_ROW4 * 16)   // 55296 bytes
// packed half area: row = 32 groups x 16B -> 36 uint4 padded
#define PK_ROW4 36
#define PK_ROWB (PK_ROW4 * 16)             // 576 B
#define W_PK_B  (BB * PK_ROWB)             // 18432
#define PK_B    ((BB + RDIM) * PK_ROWB)    // 55296 per buffer
#define DYN_SMEM (RAW_B + 2 * PK_B)        // 165888 B

__device__ float g_partial[NBLOCK];
__device__ int   g_count = 0;

__device__ __forceinline__ uint32_t smem_u32(const void* p) {
    return (uint32_t)__cvta_generic_to_shared(p);
}
__device__ __forceinline__ void bulk_cp(uint32_t dst, const void* src,
                                        uint32_t bytes, uint32_t mbar) {
    asm volatile(
        "cp.async.bulk.shared::cta.global.mbarrier::complete_tx::bytes [%0], [%1], %2, [%3];"
        :: "r"(dst), "l"(src), "r"(bytes), "r"(mbar) : "memory");
}
__device__ __forceinline__ void mbar_init(uint32_t mbar, uint32_t cnt) {
    asm volatile("mbarrier.init.shared.b64 [%0], %1;" :: "r"(mbar), "r"(cnt) : "memory");
}
__device__ __forceinline__ void mbar_expect_tx(uint32_t mbar, uint32_t bytes) {
    asm volatile("mbarrier.arrive.expect_tx.shared.b64 _, [%0], %1;"
                 :: "r"(mbar), "r"(bytes) : "memory");
}
__device__ __forceinline__ void mbar_wait(uint32_t mbar, uint32_t parity) {
    asm volatile(
        "{\n\t.reg .pred P;\n\t"
        "WL_%=:\n\t"
        "mbarrier.try_wait.parity.acquire.cta.shared::cta.b64 P, [%0], %1, 0x989680;\n\t"
        "@P bra.uni WD_%=;\n\t"
        "bra.uni WL_%=;\n\t"
        "WD_%=:\n\t}"
        :: "r"(mbar), "r"(parity) : "memory");
}
__device__ __forceinline__ void mma_f16(float* c, const uint32_t* a, const uint32_t* b) {
    asm volatile(
        "mma.sync.aligned.m16n8k16.row.col.f32.f16.f16.f32 "
        "{%0,%1,%2,%3}, {%4,%5,%6,%7}, {%8,%9}, {%0,%1,%2,%3};"
        : "+f"(c[0]), "+f"(c[1]), "+f"(c[2]), "+f"(c[3])
        : "r"(a[0]), "r"(a[1]), "r"(a[2]), "r"(a[3]), "r"(b[0]), "r"(b[1]));
}
__device__ __forceinline__ uint32_t h2_as_u32(__half2 h) {
    uint32_t u;
    memcpy(&u, &h, 4);
    return u;
}
// pack a float4 into {hi01, hi23, lo01, lo23} (f16x2 each); accumulate squares
__device__ __forceinline__ uint4 pack_hilo(float4 v, float& sq) {
    __half2 h01 = __floats2half2_rn(v.x, v.y);
    __half2 h23 = __floats2half2_rn(v.z, v.w);
    float2 f01 = __half22float2(h01);
    float2 f23 = __half22float2(h23);
    __half2 l01 = __floats2half2_rn(v.x - f01.x, v.y - f01.y);
    __half2 l23 = __floats2half2_rn(v.z - f23.x, v.w - f23.y);
    sq = fmaf(v.x, v.x, sq); sq = fmaf(v.y, v.y, sq);
    sq = fmaf(v.z, v.z, sq); sq = fmaf(v.w, v.w, sq);
    uint4 r;
    r.x = h2_as_u32(h01); r.y = h2_as_u32(h23);
    r.z = h2_as_u32(l01); r.w = h2_as_u32(l23);
    return r;
}

__global__ __launch_bounds__(NTHREADS, 1)
void fused_kernel(const float* __restrict__ w,
                  const float* __restrict__ e,
                  const float* __restrict__ label,
                  float* __restrict__ out, int out_size)
{
    extern __shared__ __align__(16) float dyn[];
    char* const dynb = reinterpret_cast<char*>(dyn);

    __shared__ __align__(8) uint64_t mbar_sto[NCHUNK];
    __shared__ float ne_red[RDIM][5];
    __shared__ float ne_s[RDIM];
    __shared__ float nw_red[BB][9];
    __shared__ int   idx1_s[BB];
    __shared__ float fs[NBLOCK];
    __shared__ int   is_last;

    const int tid  = threadIdx.x;
    const int lane = tid & 31;
    const int wid  = tid >> 5;
    const int b0   = blockIdx.x * BB;

    // s_s aliases packed buffer 0 (dead after all MMAs)
    float (*s_s)[65] = reinterpret_cast<float (*)[65]>(dynb + RAW_B);

    uint32_t mbars[NCHUNK];
#pragma unroll
    for (int q = 0; q < NCHUNK; q++) mbars[q] = smem_u32(&mbar_sto[q]);

    if (tid == 0) {
#pragma unroll
        for (int q = 0; q < NCHUNK; q++) mbar_init(mbars[q], 1);
    }
    __syncthreads();
    if (tid == 0) {
#pragma unroll
        for (int q = 0; q < NCHUNK; q++)
            mbar_expect_tx(mbars[q], (BB + RDIM) * KC * 4);
    }
    __syncthreads();

    auto issue_chunk = [&](int q) {
        if (tid < BB + RDIM) {
            if (tid < BB)
                bulk_cp(smem_u32(dyn + tid * (RAW_ROW4 * 4)),
                        w + (size_t)(b0 + tid) * DDIM + q * KC, KC * 4, mbars[q]);
            else {
                int r = tid - BB;
                bulk_cp(smem_u32(dyn + (BB + r) * (RAW_ROW4 * 4)),
                        e + (size_t)r * DDIM + q * KC, KC * 4, mbars[q]);
            }
        }
    };
    issue_chunk(0);

    // warp tile: (kh, nh); M=32 x N=16, kh splits the chunk's 8 blocks
    const int kh = wid >> 2;          // 0..1
    const int nh = wid & 3;           // 0..3
    const int gi = lane >> 2;         // 0..7
    const int kk = lane & 3;          // 0..3

    // split-pass mappings (conflict-free: consecutive-lane phases)
    const int w_row = tid >> 3, w_gc = tid & 7;    // 8 thr/row, 4 groups each
    const int e_row = tid >> 2, e_gc = tid & 3;    // 4 thr/row, 8 groups each

    float acc[2][2][3][4];            // [m][n][term hh/hl/lh][4]
#pragma unroll
    for (int m = 0; m < 2; m++)
#pragma unroll
        for (int n = 0; n < 2; n++)
#pragma unroll
            for (int q = 0; q < 3; q++)
#pragma unroll
                for (int i = 0; i < 4; i++) acc[m][n][q][i] = 0.f;

    float nw_acc = 0.f, ne_acc = 0.f;

    for (int q = 0; q < NCHUNK; q++) {
        char* PK = dynb + RAW_B + (q & 1) * PK_B;
        mbar_wait(mbars[q], 0);

        // ---- split pass: raw fp32 -> packed {hi,lo} half tiles; norms ride along ----
        {
            const float4* wr = reinterpret_cast<const float4*>(dyn) + w_row * RAW_ROW4;
            uint4* wpk = reinterpret_cast<uint4*>(PK) + w_row * PK_ROW4;
#pragma unroll
            for (int j = 0; j < 4; j++) {
                int g = w_gc + 8 * j;
                wpk[g] = pack_hilo(wr[g], nw_acc);
            }
            const float4* er = reinterpret_cast<const float4*>(dyn)
                             + (BB + e_row) * RAW_ROW4;
            uint4* epk = reinterpret_cast<uint4*>(PK + W_PK_B) + e_row * PK_ROW4;
#pragma unroll
            for (int j = 0; j < 8; j++) {
                int g = e_gc + 4 * j;
                epk[g] = pack_hilo(er[g], ne_acc);
            }
        }
        __syncthreads();   // packed tiles visible; raw free for next chunk

        if (q + 1 < NCHUNK) issue_chunk(q + 1);   // fills raw during MMA(q)

        // ---- pure LDS + HMMA: 4 blocks of 16 K each (kh picks half) ----
        const uint4* wp = reinterpret_cast<const uint4*>(PK) + gi * PK_ROW4;
        const uint4* ep = reinterpret_cast<const uint4*>(PK + W_PK_B)
                        + (16 * nh + gi) * PK_ROW4;

#pragma unroll
        for (int blk = 0; blk < 4; blk++) {
            const int g = 4 * (kh * 4 + blk) + kk;
            uint4 W0 = wp[g];                     // row gi
            uint4 W1 = wp[8 * PK_ROW4 + g];       // row gi+8
            uint4 W2 = wp[16 * PK_ROW4 + g];      // row gi+16
            uint4 W3 = wp[24 * PK_ROW4 + g];      // row gi+24
            uint4 E0 = ep[g];                     // col group gi
            uint4 E1 = ep[8 * PK_ROW4 + g];       // col group gi+8

            uint32_t aH[2][4] = {{W0.x, W1.x, W0.y, W1.y},
                                 {W2.x, W3.x, W2.y, W3.y}};
            uint32_t aL[2][4] = {{W0.z, W1.z, W0.w, W1.w},
                                 {W2.z, W3.z, W2.w, W3.w}};
            uint32_t bH[2][2] = {{E0.x, E0.y}, {E1.x, E1.y}};
            uint32_t bL[2][2] = {{E0.z, E0.w}, {E1.z, E1.w}};

#pragma unroll
            for (int m = 0; m < 2; m++)
#pragma unroll
                for (int n = 0; n < 2; n++) {
                    mma_f16(acc[m][n][0], aH[m], bH[n]);
                    mma_f16(acc[m][n][1], aH[m], bL[n]);
                    mma_f16(acc[m][n][2], aL[m], bH[n]);
                }
        }
    }

    // ---- combine terms; two-phase deterministic kh merge into s_s ----
    float part[2][2][4];
#pragma unroll
    for (int m = 0; m < 2; m++)
#pragma unroll
        for (int n = 0; n < 2; n++)
#pragma unroll
            for (int i = 0; i < 4; i++)
                part[m][n][i] = (acc[m][n][0][i] + acc[m][n][1][i]) + acc[m][n][2][i];

    __syncthreads();   // all MMAs done; pk0 (s_s alias) dead
    if (kh == 0) {
#pragma unroll
        for (int m = 0; m < 2; m++)
#pragma unroll
            for (int n = 0; n < 2; n++) {
                const int rb = 16 * m + gi;
                const int cb = 16 * nh + 8 * n + 2 * kk;
                s_s[rb][cb]         = part[m][n][0];
                s_s[rb][cb + 1]     = part[m][n][1];
                s_s[rb + 8][cb]     = part[m][n][2];
                s_s[rb + 8][cb + 1] = part[m][n][3];
            }
    }
    nw_red[w_row][w_gc] = nw_acc;
    ne_red[e_row][e_gc] = ne_acc;
    __syncthreads();
    if (kh == 1) {
#pragma unroll
        for (int m = 0; m < 2; m++)
#pragma unroll
            for (int n = 0; n < 2; n++) {
                const int rb = 16 * m + gi;
                const int cb = 16 * nh + 8 * n + 2 * kk;
                s_s[rb][cb]         += part[m][n][0];
                s_s[rb][cb + 1]     += part[m][n][1];
                s_s[rb + 8][cb]     += part[m][n][2];
                s_s[rb + 8][cb + 1] += part[m][n][3];
            }
    }
    if (tid < RDIM)
        ne_s[tid] = ne_red[tid][0] + ne_red[tid][1] + ne_red[tid][2] + ne_red[tid][3];
    __syncthreads();

    // ---- per-row epilogue: thread tid < 32 owns row b0+tid ----
    if (tid < BB) {
        const int r = tid;
        int y = 0;
        {
            const float4* lp = reinterpret_cast<const float4*>(
                label + (size_t)(b0 + r) * RDIM);
            float lm = -1e30f;
#pragma unroll
            for (int g = 0; g < 16; g++) {
                float4 v = lp[g];
                if (v.x > lm) { lm = v.x; y = g * 4; }
                if (v.y > lm) { lm = v.y; y = g * 4 + 1; }
                if (v.z > lm) { lm = v.z; y = g * 4 + 2; }
                if (v.w > lm) { lm = v.w; y = g * 4 + 3; }
            }
        }
        float m1 = -1e30f, m2 = -1e30f, s_y = 0.f;
        int i1 = 0;
#pragma unroll
        for (int c = 0; c < RDIM; c++) {
            float sv = fmaf(-2.f, s_s[r][c], ne_s[c]);
            if (c == y) s_y = sv;
            if (sv > m1)      { m2 = m1; m1 = sv; i1 = c; }
            else if (sv > m2) { m2 = sv; }
        }
        float nw = 0.f;
#pragma unroll
        for (int k = 0; k < 8; k++) nw += nw_red[r][k];

        float plus2  = fmaxf(nw + s_y, 0.f);
        float minus2 = fmaxf(nw + ((i1 == y) ? m2 : m1), 0.f);
        float loss_b = 1.f + sqrtf(plus2) - sqrtf(minus2);
        idx1_s[r] = i1;
#pragma unroll
        for (int off = 16; off; off >>= 1)
            loss_b += __shfl_xor_sync(0xFFFFFFFFu, loss_b, off);
        if (lane == 0) g_partial[blockIdx.x] = loss_b;
    }
    __syncthreads();

    // ---- coalesced one-hot pred write (2 float4 per thread) ----
    {
        float4* op = reinterpret_cast<float4*>(out + (size_t)b0 * RDIM);
#pragma unroll
        for (int k = 0; k < 2; k++) {
            int i  = tid * 8 + k * 4;
            int bl = i >> 6;
            int r  = i & 63;
            int p  = idx1_s[bl];
            float4 v;
            v.x = (r + 0 == p) ? 1.f : 0.f;
            v.y = (r + 1 == p) ? 1.f : 0.f;
            v.z = (r + 2 == p) ? 1.f : 0.f;
            v.w = (r + 3 == p) ? 1.f : 0.f;
            op[tid * 2 + k] = v;
        }
    }

    // ---- fused finalize ----
    if (tid == 0) {
        __threadfence();
        int c = atomicAdd(&g_count, 1);
        is_last = (c == gridDim.x - 1) ? 1 : 0;
    }
    __syncthreads();
    if (is_last) {
        __threadfence();
        if (tid < NBLOCK) fs[tid] = g_partial[tid];
        __syncthreads();
#pragma unroll
        for (int off = NBLOCK / 2; off > 0; off >>= 1) {
            if (tid < off) fs[tid] += fs[tid + off];
            __syncthreads();
        }
        if (tid == 0) {
            out[out_size - 1] = fs[0] * (1.0f / (float)BDIM);
            g_count = 0;
        }
    }
}

extern "C" void kernel_launch(void* const* d_in, const int* in_sizes, int n_in,
                              void* d_out, int out_size)
{
    const float* w     = (const float*)d_in[0];   // [4096, 512]
    const float* e     = (const float*)d_in[1];   // [64, 512]
    const float* label = (const float*)d_in[2];   // [4096, 64]
    float* out = (float*)d_out;                   // pred [4096*64] ++ loss [1]

    cudaFuncSetAttribute(fused_kernel,
                         cudaFuncAttributeMaxDynamicSharedMemorySize, DYN_SMEM);
    fused_kernel<<<NBLOCK, NTHREADS, DYN_SMEM>>>(w, e, label, out, out_size);
}